// round 7
// baseline (speedup 1.0000x reference)
#include <cuda_runtime.h>

// ---------------------------------------------------------------------------
// EdgeNetwork: per-node factorization + 2 edges/thread (scalar math).
//   pre_k : xs[n] = x[n]@W1a + b1 + vp[batch[n]]@W1c ; xb[n] = x[n]@W1b
//   edge_k: h = xs[s]+xb[d]; 3x(LN+tanh) H=8 in regs, K-folded tanh,
//           next-iteration index prefetch, persistent grid.
//   R7: block 64 x 7 blocks/SM (reg cap 146 > natural 142) => 14 warps/SM.
// ---------------------------------------------------------------------------

#define NODE_CAP 131072
#define KLOG2E 2.8853900817779268f   // 2*log2(e)

__device__ __align__(16) float g_xs[NODE_CAP * 8];
__device__ __align__(16) float g_xb[NODE_CAP * 8];

__device__ __forceinline__ int detect_is64(const int* __restrict__ ei) {
    int nz = 0;
#pragma unroll
    for (int i = 1; i < 16; i += 2) nz |= ei[i];
    return nz == 0;
}

// ---------------------------------------------------------------------------
// Per-node precompute
// ---------------------------------------------------------------------------
__global__ void __launch_bounds__(256) pre_k(
    const float* __restrict__ x, const int* __restrict__ batch_raw,
    const float* __restrict__ vp, const float* __restrict__ W1,
    const float* __restrict__ b1, const int* __restrict__ ei, int N, int G)
{
    __shared__ float sW1[48 * 8];
    __shared__ float svp[64 * 16];
    __shared__ float sb1[8];
    __shared__ int sflag;
    int t = threadIdx.x;
    if (t == 0) sflag = detect_is64(ei);
    for (int i = t; i < 384; i += blockDim.x) sW1[i] = W1[i];
    int gv = G * 16; if (gv > 1024) gv = 1024;
    for (int i = t; i < gv; i += blockDim.x) svp[i] = vp[i];
    if (t < 8) sb1[t] = b1[t];
    __syncthreads();

    int n = blockIdx.x * blockDim.x + t;
    if (n >= N) return;

    int g = sflag ? batch_raw[2 * n] : batch_raw[n];

    float xi[16];
    const float* xr = x + (size_t)n * 16;
#pragma unroll
    for (int k = 0; k < 16; k += 4) {
        float4 v = *(const float4*)(xr + k);
        xi[k] = v.x; xi[k + 1] = v.y; xi[k + 2] = v.z; xi[k + 3] = v.w;
    }
    const float* vg = svp + g * 16;

    float xs[8], xb[8];
#pragma unroll
    for (int j = 0; j < 8; j++) {
        float a = sb1[j];
        float b = 0.0f;
#pragma unroll
        for (int k = 0; k < 16; k++) {
            a = fmaf(xi[k], sW1[k * 8 + j], a);
            a = fmaf(vg[k], sW1[(32 + k) * 8 + j], a);
            b = fmaf(xi[k], sW1[(16 + k) * 8 + j], b);
        }
        xs[j] = a; xb[j] = b;
    }
    float4* o1 = (float4*)(g_xs + (size_t)n * 8);
    o1[0] = make_float4(xs[0], xs[1], xs[2], xs[3]);
    o1[1] = make_float4(xs[4], xs[5], xs[6], xs[7]);
    float4* o2 = (float4*)(g_xb + (size_t)n * 8);
    o2[0] = make_float4(xb[0], xb[1], xb[2], xb[3]);
    o2[1] = make_float4(xb[4], xb[5], xb[6], xb[7]);
}

// ---------------------------------------------------------------------------
// LN + tanh, K-folded: z = (h-mu)*(K*r)*g + K*be, t = 1 - 2*rcp(ex2(z)+1).
// 5 fma-pipe + 2 MUFU per channel. In-place on h[8].
// ---------------------------------------------------------------------------
__device__ __forceinline__ void ln_tanh(float h[8], const float* __restrict__ g,
                                        const float* __restrict__ kbe) {
    float s = ((h[0] + h[1]) + (h[2] + h[3])) + ((h[4] + h[5]) + (h[6] + h[7]));
    float ss = 0.0f;
#pragma unroll
    for (int j = 0; j < 8; j++) ss = fmaf(h[j], h[j], ss);
    float mu = s * 0.125f;
    float var = fmaf(-mu, mu, ss * 0.125f);
    float r = rsqrtf(var + 1e-5f);
    float P = r * KLOG2E;
#pragma unroll
    for (int j = 0; j < 8; j++) {
        float w = P * g[j];
        float c = fmaf(-mu, w, kbe[j]);
        float z = fmaf(h[j], w, c);
        float q, rc;
        asm("ex2.approx.f32 %0, %1;" : "=f"(q) : "f"(z));
        float sum = q + 1.0f;
        asm("rcp.approx.f32 %0, %1;" : "=f"(rc) : "f"(sum));
        h[j] = fmaf(-2.0f, rc, 1.0f);
    }
}

__device__ __forceinline__ void gemm8(const float hin[8], float hout[8],
                                      const float* __restrict__ W,
                                      const float* __restrict__ b) {
#pragma unroll
    for (int j = 0; j < 8; j++) {
        float a = b[j];
#pragma unroll
        for (int k = 0; k < 8; k++) a = fmaf(hin[k], W[k * 8 + j], a);
        hout[j] = a;
    }
}

__device__ __forceinline__ void load_idx(
    const int* __restrict__ ei, size_t E, int e0, int is64,
    int& s0, int& s1, int& d0, int& d1)
{
    if (is64) {
        int4 sw = *(const int4*)(ei + 2 * (size_t)e0);
        int4 dw = *(const int4*)(ei + 2 * (E + (size_t)e0));
        s0 = sw.x; s1 = sw.z; d0 = dw.x; d1 = dw.z;
    } else {
        int2 sw = *(const int2*)(ei + e0);
        int2 dw = *(const int2*)(ei + E + (size_t)e0);
        s0 = sw.x; s1 = sw.y; d0 = dw.x; d1 = dw.y;
    }
}

__global__ void __launch_bounds__(64, 7) edge_k(
    const int* __restrict__ ei, int E,
    const float* __restrict__ g1, const float* __restrict__ be1,
    const float* __restrict__ W2, const float* __restrict__ b2,
    const float* __restrict__ g2, const float* __restrict__ be2,
    const float* __restrict__ W3, const float* __restrict__ b3,
    const float* __restrict__ g3, const float* __restrict__ be3,
    const float* __restrict__ W4, const float* __restrict__ b4,
    float* __restrict__ out)
{
    __shared__ float sW2[64], sW3[64], sW4[8];
    __shared__ float sv[64];  // g1,Kbe1,b2,g2,Kbe2,b3,g3,Kbe3
    __shared__ float sb4;
    __shared__ int sflag;
    int t = threadIdx.x;
    if (t == 0) { sflag = detect_is64(ei); sb4 = b4[0]; }
    if (t < 64) { sW2[t] = W2[t]; sW3[t] = W3[t]; }
    if (t < 8) {
        sW4[t] = W4[t];
        sv[t]      = g1[t];  sv[8 + t]  = KLOG2E * be1[t];
        sv[16 + t] = b2[t];  sv[24 + t] = g2[t];  sv[32 + t] = KLOG2E * be2[t];
        sv[40 + t] = b3[t];  sv[48 + t] = g3[t];  sv[56 + t] = KLOG2E * be3[t];
    }
    __syncthreads();

    const float* sg1 = sv;       const float* skb1 = sv + 8;
    const float* sb2 = sv + 16;  const float* sg2  = sv + 24; const float* skb2 = sv + 32;
    const float* sb3 = sv + 40;  const float* sg3  = sv + 48; const float* skb3 = sv + 56;

    const int is64 = sflag;
    const int stride2 = gridDim.x * blockDim.x * 2;
    int e0 = (blockIdx.x * blockDim.x + t) * 2;

    int s0 = 0, s1 = 0, d0 = 0, d1 = 0;
    bool pv = (e0 + 1 < E);
    if (pv) load_idx(ei, (size_t)E, e0, is64, s0, s1, d0, d1);

    while (e0 < E) {
        int e1 = e0 + stride2;
        if (pv) {
            // prefetch next iteration's indices
            int ns0 = 0, ns1 = 0, nd0 = 0, nd1 = 0;
            bool npv = (e1 + 1 < E);
            if (npv) load_idx(ei, (size_t)E, e1, is64, ns0, ns1, nd0, nd1);

            const float4* apA = (const float4*)(g_xs + (size_t)s0 * 8);
            const float4* bpA = (const float4*)(g_xb + (size_t)d0 * 8);
            const float4* apB = (const float4*)(g_xs + (size_t)s1 * 8);
            const float4* bpB = (const float4*)(g_xb + (size_t)d1 * 8);
            float4 a0A = apA[0], a1A = apA[1], c0A = bpA[0], c1A = bpA[1];
            float4 a0B = apB[0], a1B = apB[1], c0B = bpB[0], c1B = bpB[1];

            float hA[8] = { a0A.x + c0A.x, a0A.y + c0A.y, a0A.z + c0A.z, a0A.w + c0A.w,
                            a1A.x + c1A.x, a1A.y + c1A.y, a1A.z + c1A.z, a1A.w + c1A.w };
            float hB[8] = { a0B.x + c0B.x, a0B.y + c0B.y, a0B.z + c0B.z, a0B.w + c0B.w,
                            a1B.x + c1B.x, a1B.y + c1B.y, a1B.z + c1B.z, a1B.w + c1B.w };

            ln_tanh(hA, sg1, skb1);            ln_tanh(hB, sg1, skb1);
            float h2A[8], h2B[8];
            gemm8(hA, h2A, sW2, sb2);          gemm8(hB, h2B, sW2, sb2);
            ln_tanh(h2A, sg2, skb2);           ln_tanh(h2B, sg2, skb2);
            float h3A[8], h3B[8];
            gemm8(h2A, h3A, sW3, sb3);         gemm8(h2B, h3B, sW3, sb3);
            ln_tanh(h3A, sg3, skb3);           ln_tanh(h3B, sg3, skb3);

            float oA = sb4, oB = sb4;
#pragma unroll
            for (int k = 0; k < 8; k++) { oA = fmaf(h3A[k], sW4[k], oA);
                                          oB = fmaf(h3B[k], sW4[k], oB); }
            *(float2*)(out + e0) = make_float2(oA, oB);

            s0 = ns0; s1 = ns1; d0 = nd0; d1 = nd1;
            pv = npv;
        } else {
            // scalar tail (e0 == E-1, only when E is odd)
            int s, d;
            if (is64) { s = ei[2 * (size_t)e0]; d = ei[2 * ((size_t)E + e0)]; }
            else      { s = ei[e0];             d = ei[(size_t)E + e0]; }
            const float4* ap = (const float4*)(g_xs + (size_t)s * 8);
            const float4* bp = (const float4*)(g_xb + (size_t)d * 8);
            float4 a0 = ap[0], a1 = ap[1], c0 = bp[0], c1 = bp[1];
            float h[8] = { a0.x + c0.x, a0.y + c0.y, a0.z + c0.z, a0.w + c0.w,
                           a1.x + c1.x, a1.y + c1.y, a1.z + c1.z, a1.w + c1.w };
            ln_tanh(h, sg1, skb1);
            float h2[8]; gemm8(h, h2, sW2, sb2);
            ln_tanh(h2, sg2, skb2);
            float h3[8]; gemm8(h2, h3, sW3, sb3);
            ln_tanh(h3, sg3, skb3);
            float o = sb4;
#pragma unroll
            for (int k = 0; k < 8; k++) o = fmaf(h3[k], sW4[k], o);
            out[e0] = o;
            pv = (e1 + 1 < E);
            if (pv) load_idx(ei, (size_t)E, e1, is64, s0, s1, d0, d1);
        }
        e0 = e1;
    }
}

// ---------------------------------------------------------------------------
extern "C" void kernel_launch(void* const* d_in, const int* in_sizes, int n_in,
                              void* d_out, int out_size)
{
    const float* x     = (const float*)d_in[0];
    const int*   ei    = (const int*)d_in[1];
    const float* vp    = (const float*)d_in[2];
    const int*   batch = (const int*)d_in[3];
    const float* W1  = (const float*)d_in[4];
    const float* b1  = (const float*)d_in[5];
    const float* g1  = (const float*)d_in[6];
    const float* be1 = (const float*)d_in[7];
    const float* W2  = (const float*)d_in[8];
    const float* b2  = (const float*)d_in[9];
    const float* g2  = (const float*)d_in[10];
    const float* be2 = (const float*)d_in[11];
    const float* W3  = (const float*)d_in[12];
    const float* b3  = (const float*)d_in[13];
    const float* g3  = (const float*)d_in[14];
    const float* be3 = (const float*)d_in[15];
    const float* W4  = (const float*)d_in[16];
    const float* b4  = (const float*)d_in[17];

    int N = in_sizes[0] / 16;
    int E = in_sizes[1] / 2;
    int G = in_sizes[2] / 16;

    int pb = (N + 255) / 256;
    pre_k<<<pb, 256>>>(x, batch, vp, W1, b1, ei, N, G);

    // persistent 1-wave grid: 7 blocks/SM x 148 SMs x 64 threads = 14 warps/SM
    int eb = 148 * 7;
    long long need = ((long long)E / 2 + 63) / 64;
    if (need < eb) eb = (int)(need > 0 ? need : 1);
    edge_k<<<eb, 64>>>(ei, E, g1, be1, W2, b2, g2, be2, W3, b3, g3, be3,
                       W4, b4, (float*)d_out);
}

// round 8
// speedup vs baseline: 1.1378x; 1.1378x over previous
#include <cuda_runtime.h>

// ---------------------------------------------------------------------------
// EdgeNetwork: per-node factorization + 2 edges/thread (scalar math).
//   pre_k : xs[n] = x[n]@W1a + b1 + vp[batch[n]]@W1c ; xb[n] = x[n]@W1b
//   edge_k: h = xs[s]+xb[d]; 3x(LN+tanh) H=8 in regs, K-folded tanh,
//           next-iteration index prefetch, persistent grid (R6 config).
//   R8: runtime-detected uniform LN affine (gamma==1, beta==0) fast path:
//       z = fma(h, P, -mu*P) -- 1 fma/channel instead of 3, no g/be LDS.
// ---------------------------------------------------------------------------

#define NODE_CAP 131072
#define KLOG2E 2.8853900817779268f   // 2*log2(e)

__device__ __align__(16) float g_xs[NODE_CAP * 8];
__device__ __align__(16) float g_xb[NODE_CAP * 8];

__device__ __forceinline__ int detect_is64(const int* __restrict__ ei) {
    int nz = 0;
#pragma unroll
    for (int i = 1; i < 16; i += 2) nz |= ei[i];
    return nz == 0;
}

// ---------------------------------------------------------------------------
// Per-node precompute
// ---------------------------------------------------------------------------
__global__ void __launch_bounds__(256) pre_k(
    const float* __restrict__ x, const int* __restrict__ batch_raw,
    const float* __restrict__ vp, const float* __restrict__ W1,
    const float* __restrict__ b1, const int* __restrict__ ei, int N, int G)
{
    __shared__ float sW1[48 * 8];
    __shared__ float svp[64 * 16];
    __shared__ float sb1[8];
    __shared__ int sflag;
    int t = threadIdx.x;
    if (t == 0) sflag = detect_is64(ei);
    for (int i = t; i < 384; i += blockDim.x) sW1[i] = W1[i];
    int gv = G * 16; if (gv > 1024) gv = 1024;
    for (int i = t; i < gv; i += blockDim.x) svp[i] = vp[i];
    if (t < 8) sb1[t] = b1[t];
    __syncthreads();

    int n = blockIdx.x * blockDim.x + t;
    if (n >= N) return;

    int g = sflag ? batch_raw[2 * n] : batch_raw[n];

    float xi[16];
    const float* xr = x + (size_t)n * 16;
#pragma unroll
    for (int k = 0; k < 16; k += 4) {
        float4 v = *(const float4*)(xr + k);
        xi[k] = v.x; xi[k + 1] = v.y; xi[k + 2] = v.z; xi[k + 3] = v.w;
    }
    const float* vg = svp + g * 16;

    float xs[8], xb[8];
#pragma unroll
    for (int j = 0; j < 8; j++) {
        float a = sb1[j];
        float b = 0.0f;
#pragma unroll
        for (int k = 0; k < 16; k++) {
            a = fmaf(xi[k], sW1[k * 8 + j], a);
            a = fmaf(vg[k], sW1[(32 + k) * 8 + j], a);
            b = fmaf(xi[k], sW1[(16 + k) * 8 + j], b);
        }
        xs[j] = a; xb[j] = b;
    }
    float4* o1 = (float4*)(g_xs + (size_t)n * 8);
    o1[0] = make_float4(xs[0], xs[1], xs[2], xs[3]);
    o1[1] = make_float4(xs[4], xs[5], xs[6], xs[7]);
    float4* o2 = (float4*)(g_xb + (size_t)n * 8);
    o2[0] = make_float4(xb[0], xb[1], xb[2], xb[3]);
    o2[1] = make_float4(xb[4], xb[5], xb[6], xb[7]);
}

// ---------------------------------------------------------------------------
// tanh(z2) where z2 = 2*log2(e)*z : t = 1 - 2*rcp(ex2(z2)+1).
// ---------------------------------------------------------------------------
__device__ __forceinline__ float tanh_from_z2(float z2) {
    float q, rc;
    asm("ex2.approx.f32 %0, %1;" : "=f"(q) : "f"(z2));
    float sum = q + 1.0f;
    asm("rcp.approx.f32 %0, %1;" : "=f"(rc) : "f"(sum));
    return fmaf(-2.0f, rc, 1.0f);
}

// LN stats shared by both paths: returns mu and P = rsqrt(var+eps)*K.
__device__ __forceinline__ void ln_stats(const float h[8], float& mu, float& P) {
    float s = ((h[0] + h[1]) + (h[2] + h[3])) + ((h[4] + h[5]) + (h[6] + h[7]));
    float ss = 0.0f;
#pragma unroll
    for (int j = 0; j < 8; j++) ss = fmaf(h[j], h[j], ss);
    mu = s * 0.125f;
    float var = fmaf(-mu, mu, ss * 0.125f);
    P = rsqrtf(var + 1e-5f) * KLOG2E;
}

// Fast path: gamma==1, beta==0.  z2 = (h-mu)*P = fma(h, P, -mu*P).
__device__ __forceinline__ void ln_tanh_u(float h[8]) {
    float mu, P;
    ln_stats(h, mu, P);
    float c = -mu * P;
#pragma unroll
    for (int j = 0; j < 8; j++)
        h[j] = tanh_from_z2(fmaf(h[j], P, c));
}

// General path: z2 = (h-mu)*P*g[j] + K*be[j].
__device__ __forceinline__ void ln_tanh_g(float h[8], const float* __restrict__ g,
                                          const float* __restrict__ kbe) {
    float mu, P;
    ln_stats(h, mu, P);
#pragma unroll
    for (int j = 0; j < 8; j++) {
        float w = P * g[j];
        float c = fmaf(-mu, w, kbe[j]);
        h[j] = tanh_from_z2(fmaf(h[j], w, c));
    }
}

__device__ __forceinline__ void gemm8(const float hin[8], float hout[8],
                                      const float* __restrict__ W,
                                      const float* __restrict__ b) {
#pragma unroll
    for (int j = 0; j < 8; j++) {
        float a = b[j];
#pragma unroll
        for (int k = 0; k < 8; k++) a = fmaf(hin[k], W[k * 8 + j], a);
        hout[j] = a;
    }
}

__device__ __forceinline__ void load_idx(
    const int* __restrict__ ei, size_t E, int e0, int is64,
    int& s0, int& s1, int& d0, int& d1)
{
    if (is64) {
        int4 sw = *(const int4*)(ei + 2 * (size_t)e0);
        int4 dw = *(const int4*)(ei + 2 * (E + (size_t)e0));
        s0 = sw.x; s1 = sw.z; d0 = dw.x; d1 = dw.z;
    } else {
        int2 sw = *(const int2*)(ei + e0);
        int2 dw = *(const int2*)(ei + E + (size_t)e0);
        s0 = sw.x; s1 = sw.y; d0 = dw.x; d1 = dw.y;
    }
}

__global__ void __launch_bounds__(128, 3) edge_k(
    const int* __restrict__ ei, int E,
    const float* __restrict__ g1, const float* __restrict__ be1,
    const float* __restrict__ W2, const float* __restrict__ b2,
    const float* __restrict__ g2, const float* __restrict__ be2,
    const float* __restrict__ W3, const float* __restrict__ b3,
    const float* __restrict__ g3, const float* __restrict__ be3,
    const float* __restrict__ W4, const float* __restrict__ b4,
    float* __restrict__ out)
{
    __shared__ float sW2[64], sW3[64], sW4[8];
    __shared__ float sv[64];  // g1,Kbe1,b2,g2,Kbe2,b3,g3,Kbe3
    __shared__ float sb4;
    __shared__ int sflag, suni;
    int t = threadIdx.x;
    if (t == 0) {
        sflag = detect_is64(ei); sb4 = b4[0];
        // uniform-affine detection: all gammas == 1, all betas == 0
        int u = 1;
#pragma unroll
        for (int j = 0; j < 8; j++) {
            u &= (g1[j] == 1.0f) & (be1[j] == 0.0f);
            u &= (g2[j] == 1.0f) & (be2[j] == 0.0f);
            u &= (g3[j] == 1.0f) & (be3[j] == 0.0f);
        }
        suni = u;
    }
    if (t < 64) { sW2[t] = W2[t]; sW3[t] = W3[t]; }
    if (t < 8) {
        sW4[t] = W4[t];
        sv[t]      = g1[t];  sv[8 + t]  = KLOG2E * be1[t];
        sv[16 + t] = b2[t];  sv[24 + t] = g2[t];  sv[32 + t] = KLOG2E * be2[t];
        sv[40 + t] = b3[t];  sv[48 + t] = g3[t];  sv[56 + t] = KLOG2E * be3[t];
    }
    __syncthreads();

    const float* sg1 = sv;       const float* skb1 = sv + 8;
    const float* sb2 = sv + 16;  const float* sg2  = sv + 24; const float* skb2 = sv + 32;
    const float* sb3 = sv + 40;  const float* sg3  = sv + 48; const float* skb3 = sv + 56;

    const int is64 = sflag;
    const int uni  = suni;
    const int stride2 = gridDim.x * blockDim.x * 2;
    int e0 = (blockIdx.x * blockDim.x + t) * 2;

    int s0 = 0, s1 = 0, d0 = 0, d1 = 0;
    bool pv = (e0 + 1 < E);
    if (pv) load_idx(ei, (size_t)E, e0, is64, s0, s1, d0, d1);

    while (e0 < E) {
        int e1 = e0 + stride2;
        if (pv) {
            // prefetch next iteration's indices
            int ns0 = 0, ns1 = 0, nd0 = 0, nd1 = 0;
            bool npv = (e1 + 1 < E);
            if (npv) load_idx(ei, (size_t)E, e1, is64, ns0, ns1, nd0, nd1);

            const float4* apA = (const float4*)(g_xs + (size_t)s0 * 8);
            const float4* bpA = (const float4*)(g_xb + (size_t)d0 * 8);
            const float4* apB = (const float4*)(g_xs + (size_t)s1 * 8);
            const float4* bpB = (const float4*)(g_xb + (size_t)d1 * 8);
            float4 a0A = apA[0], a1A = apA[1], c0A = bpA[0], c1A = bpA[1];
            float4 a0B = apB[0], a1B = apB[1], c0B = bpB[0], c1B = bpB[1];

            float hA[8] = { a0A.x + c0A.x, a0A.y + c0A.y, a0A.z + c0A.z, a0A.w + c0A.w,
                            a1A.x + c1A.x, a1A.y + c1A.y, a1A.z + c1A.z, a1A.w + c1A.w };
            float hB[8] = { a0B.x + c0B.x, a0B.y + c0B.y, a0B.z + c0B.z, a0B.w + c0B.w,
                            a1B.x + c1B.x, a1B.y + c1B.y, a1B.z + c1B.z, a1B.w + c1B.w };

            float h2A[8], h2B[8], h3A[8], h3B[8];
            if (uni) {
                ln_tanh_u(hA);                    ln_tanh_u(hB);
                gemm8(hA, h2A, sW2, sb2);         gemm8(hB, h2B, sW2, sb2);
                ln_tanh_u(h2A);                   ln_tanh_u(h2B);
                gemm8(h2A, h3A, sW3, sb3);        gemm8(h2B, h3B, sW3, sb3);
                ln_tanh_u(h3A);                   ln_tanh_u(h3B);
            } else {
                ln_tanh_g(hA, sg1, skb1);         ln_tanh_g(hB, sg1, skb1);
                gemm8(hA, h2A, sW2, sb2);         gemm8(hB, h2B, sW2, sb2);
                ln_tanh_g(h2A, sg2, skb2);        ln_tanh_g(h2B, sg2, skb2);
                gemm8(h2A, h3A, sW3, sb3);        gemm8(h2B, h3B, sW3, sb3);
                ln_tanh_g(h3A, sg3, skb3);        ln_tanh_g(h3B, sg3, skb3);
            }

            float oA = sb4, oB = sb4;
#pragma unroll
            for (int k = 0; k < 8; k++) { oA = fmaf(h3A[k], sW4[k], oA);
                                          oB = fmaf(h3B[k], sW4[k], oB); }
            *(float2*)(out + e0) = make_float2(oA, oB);

            s0 = ns0; s1 = ns1; d0 = nd0; d1 = nd1;
            pv = npv;
        } else {
            // scalar tail (e0 == E-1, only when E is odd)
            int s, d;
            if (is64) { s = ei[2 * (size_t)e0]; d = ei[2 * ((size_t)E + e0)]; }
            else      { s = ei[e0];             d = ei[(size_t)E + e0]; }
            const float4* ap = (const float4*)(g_xs + (size_t)s * 8);
            const float4* bp = (const float4*)(g_xb + (size_t)d * 8);
            float4 a0 = ap[0], a1 = ap[1], c0 = bp[0], c1 = bp[1];
            float h[8] = { a0.x + c0.x, a0.y + c0.y, a0.z + c0.z, a0.w + c0.w,
                           a1.x + c1.x, a1.y + c1.y, a1.z + c1.z, a1.w + c1.w };
            float h2[8], h3[8];
            if (uni) {
                ln_tanh_u(h);
                gemm8(h, h2, sW2, sb2);
                ln_tanh_u(h2);
                gemm8(h2, h3, sW3, sb3);
                ln_tanh_u(h3);
            } else {
                ln_tanh_g(h, sg1, skb1);
                gemm8(h, h2, sW2, sb2);
                ln_tanh_g(h2, sg2, skb2);
                gemm8(h2, h3, sW3, sb3);
                ln_tanh_g(h3, sg3, skb3);
            }
            float o = sb4;
#pragma unroll
            for (int k = 0; k < 8; k++) o = fmaf(h3[k], sW4[k], o);
            out[e0] = o;
            pv = (e1 + 1 < E);
            if (pv) load_idx(ei, (size_t)E, e1, is64, s0, s1, d0, d1);
        }
        e0 = e1;
    }
}

// ---------------------------------------------------------------------------
extern "C" void kernel_launch(void* const* d_in, const int* in_sizes, int n_in,
                              void* d_out, int out_size)
{
    const float* x     = (const float*)d_in[0];
    const int*   ei    = (const int*)d_in[1];
    const float* vp    = (const float*)d_in[2];
    const int*   batch = (const int*)d_in[3];
    const float* W1  = (const float*)d_in[4];
    const float* b1  = (const float*)d_in[5];
    const float* g1  = (const float*)d_in[6];
    const float* be1 = (const float*)d_in[7];
    const float* W2  = (const float*)d_in[8];
    const float* b2  = (const float*)d_in[9];
    const float* g2  = (const float*)d_in[10];
    const float* be2 = (const float*)d_in[11];
    const float* W3  = (const float*)d_in[12];
    const float* b3  = (const float*)d_in[13];
    const float* g3  = (const float*)d_in[14];
    const float* be3 = (const float*)d_in[15];
    const float* W4  = (const float*)d_in[16];
    const float* b4  = (const float*)d_in[17];

    int N = in_sizes[0] / 16;
    int E = in_sizes[1] / 2;
    int G = in_sizes[2] / 16;

    int pb = (N + 255) / 256;
    pre_k<<<pb, 256>>>(x, batch, vp, W1, b1, ei, N, G);

    // persistent 1-wave grid: 3 blocks/SM x 148 SMs (R6 config)
    int eb = 444;
    long long need = ((long long)E / 2 + 127) / 128;
    if (need < eb) eb = (int)(need > 0 ? need : 1);
    edge_k<<<eb, 128>>>(ei, E, g1, be1, W2, b2, g2, be2, W3, b3, g3, be3,
                        W4, b4, (float*)d_out);
}

// round 9
// speedup vs baseline: 1.1645x; 1.0235x over previous
#include <cuda_runtime.h>

// ---------------------------------------------------------------------------
// EdgeNetwork: per-node factorization + 2 edges/thread (scalar math).
//   pre_k : xs[n] = x[n]@W1a + b1 + vp[batch[n]]@W1c ; xb[n] = x[n]@W1b
//   edge_k: h = xs[s]+xb[d]; 3x(LN+tanh) H=8 in regs, K-folded tanh,
//           next-iteration index prefetch, persistent grid.
//   R8: runtime uniform-affine LN fast path (gamma==1, beta==0).
//   R9: natural regs==128 => __launch_bounds__(128,4): 16 warps/SM, grid 592.
// ---------------------------------------------------------------------------

#define NODE_CAP 131072
#define KLOG2E 2.8853900817779268f   // 2*log2(e)

__device__ __align__(16) float g_xs[NODE_CAP * 8];
__device__ __align__(16) float g_xb[NODE_CAP * 8];

__device__ __forceinline__ int detect_is64(const int* __restrict__ ei) {
    int nz = 0;
#pragma unroll
    for (int i = 1; i < 16; i += 2) nz |= ei[i];
    return nz == 0;
}

// ---------------------------------------------------------------------------
// Per-node precompute
// ---------------------------------------------------------------------------
__global__ void __launch_bounds__(256) pre_k(
    const float* __restrict__ x, const int* __restrict__ batch_raw,
    const float* __restrict__ vp, const float* __restrict__ W1,
    const float* __restrict__ b1, const int* __restrict__ ei, int N, int G)
{
    __shared__ float sW1[48 * 8];
    __shared__ float svp[64 * 16];
    __shared__ float sb1[8];
    __shared__ int sflag;
    int t = threadIdx.x;
    if (t == 0) sflag = detect_is64(ei);
    for (int i = t; i < 384; i += blockDim.x) sW1[i] = W1[i];
    int gv = G * 16; if (gv > 1024) gv = 1024;
    for (int i = t; i < gv; i += blockDim.x) svp[i] = vp[i];
    if (t < 8) sb1[t] = b1[t];
    __syncthreads();

    int n = blockIdx.x * blockDim.x + t;
    if (n >= N) return;

    int g = sflag ? batch_raw[2 * n] : batch_raw[n];

    float xi[16];
    const float* xr = x + (size_t)n * 16;
#pragma unroll
    for (int k = 0; k < 16; k += 4) {
        float4 v = *(const float4*)(xr + k);
        xi[k] = v.x; xi[k + 1] = v.y; xi[k + 2] = v.z; xi[k + 3] = v.w;
    }
    const float* vg = svp + g * 16;

    float xs[8], xb[8];
#pragma unroll
    for (int j = 0; j < 8; j++) {
        float a = sb1[j];
        float b = 0.0f;
#pragma unroll
        for (int k = 0; k < 16; k++) {
            a = fmaf(xi[k], sW1[k * 8 + j], a);
            a = fmaf(vg[k], sW1[(32 + k) * 8 + j], a);
            b = fmaf(xi[k], sW1[(16 + k) * 8 + j], b);
        }
        xs[j] = a; xb[j] = b;
    }
    float4* o1 = (float4*)(g_xs + (size_t)n * 8);
    o1[0] = make_float4(xs[0], xs[1], xs[2], xs[3]);
    o1[1] = make_float4(xs[4], xs[5], xs[6], xs[7]);
    float4* o2 = (float4*)(g_xb + (size_t)n * 8);
    o2[0] = make_float4(xb[0], xb[1], xb[2], xb[3]);
    o2[1] = make_float4(xb[4], xb[5], xb[6], xb[7]);
}

// ---------------------------------------------------------------------------
// tanh(z2) where z2 = 2*log2(e)*z : t = 1 - 2*rcp(ex2(z2)+1).
// ---------------------------------------------------------------------------
__device__ __forceinline__ float tanh_from_z2(float z2) {
    float q, rc;
    asm("ex2.approx.f32 %0, %1;" : "=f"(q) : "f"(z2));
    float sum = q + 1.0f;
    asm("rcp.approx.f32 %0, %1;" : "=f"(rc) : "f"(sum));
    return fmaf(-2.0f, rc, 1.0f);
}

// LN stats shared by both paths: returns mu and P = rsqrt(var+eps)*K.
__device__ __forceinline__ void ln_stats(const float h[8], float& mu, float& P) {
    float s = ((h[0] + h[1]) + (h[2] + h[3])) + ((h[4] + h[5]) + (h[6] + h[7]));
    float ss = 0.0f;
#pragma unroll
    for (int j = 0; j < 8; j++) ss = fmaf(h[j], h[j], ss);
    mu = s * 0.125f;
    float var = fmaf(-mu, mu, ss * 0.125f);
    P = rsqrtf(var + 1e-5f) * KLOG2E;
}

// Fast path: gamma==1, beta==0.  z2 = (h-mu)*P = fma(h, P, -mu*P).
__device__ __forceinline__ void ln_tanh_u(float h[8]) {
    float mu, P;
    ln_stats(h, mu, P);
    float c = -mu * P;
#pragma unroll
    for (int j = 0; j < 8; j++)
        h[j] = tanh_from_z2(fmaf(h[j], P, c));
}

// General path: z2 = (h-mu)*P*g[j] + K*be[j].
__device__ __forceinline__ void ln_tanh_g(float h[8], const float* __restrict__ g,
                                          const float* __restrict__ kbe) {
    float mu, P;
    ln_stats(h, mu, P);
#pragma unroll
    for (int j = 0; j < 8; j++) {
        float w = P * g[j];
        float c = fmaf(-mu, w, kbe[j]);
        h[j] = tanh_from_z2(fmaf(h[j], w, c));
    }
}

__device__ __forceinline__ void gemm8(const float hin[8], float hout[8],
                                      const float* __restrict__ W,
                                      const float* __restrict__ b) {
#pragma unroll
    for (int j = 0; j < 8; j++) {
        float a = b[j];
#pragma unroll
        for (int k = 0; k < 8; k++) a = fmaf(hin[k], W[k * 8 + j], a);
        hout[j] = a;
    }
}

__device__ __forceinline__ void load_idx(
    const int* __restrict__ ei, size_t E, int e0, int is64,
    int& s0, int& s1, int& d0, int& d1)
{
    if (is64) {
        int4 sw = *(const int4*)(ei + 2 * (size_t)e0);
        int4 dw = *(const int4*)(ei + 2 * (E + (size_t)e0));
        s0 = sw.x; s1 = sw.z; d0 = dw.x; d1 = dw.z;
    } else {
        int2 sw = *(const int2*)(ei + e0);
        int2 dw = *(const int2*)(ei + E + (size_t)e0);
        s0 = sw.x; s1 = sw.y; d0 = dw.x; d1 = dw.y;
    }
}

__global__ void __launch_bounds__(128, 4) edge_k(
    const int* __restrict__ ei, int E,
    const float* __restrict__ g1, const float* __restrict__ be1,
    const float* __restrict__ W2, const float* __restrict__ b2,
    const float* __restrict__ g2, const float* __restrict__ be2,
    const float* __restrict__ W3, const float* __restrict__ b3,
    const float* __restrict__ g3, const float* __restrict__ be3,
    const float* __restrict__ W4, const float* __restrict__ b4,
    float* __restrict__ out)
{
    __shared__ float sW2[64], sW3[64], sW4[8];
    __shared__ float sv[64];  // g1,Kbe1,b2,g2,Kbe2,b3,g3,Kbe3
    __shared__ float sb4;
    __shared__ int sflag, suni;
    int t = threadIdx.x;
    if (t == 0) {
        sflag = detect_is64(ei); sb4 = b4[0];
        int u = 1;
#pragma unroll
        for (int j = 0; j < 8; j++) {
            u &= (g1[j] == 1.0f) & (be1[j] == 0.0f);
            u &= (g2[j] == 1.0f) & (be2[j] == 0.0f);
            u &= (g3[j] == 1.0f) & (be3[j] == 0.0f);
        }
        suni = u;
    }
    if (t < 64) { sW2[t] = W2[t]; sW3[t] = W3[t]; }
    if (t < 8) {
        sW4[t] = W4[t];
        sv[t]      = g1[t];  sv[8 + t]  = KLOG2E * be1[t];
        sv[16 + t] = b2[t];  sv[24 + t] = g2[t];  sv[32 + t] = KLOG2E * be2[t];
        sv[40 + t] = b3[t];  sv[48 + t] = g3[t];  sv[56 + t] = KLOG2E * be3[t];
    }
    __syncthreads();

    const float* sg1 = sv;       const float* skb1 = sv + 8;
    const float* sb2 = sv + 16;  const float* sg2  = sv + 24; const float* skb2 = sv + 32;
    const float* sb3 = sv + 40;  const float* sg3  = sv + 48; const float* skb3 = sv + 56;

    const int is64 = sflag;
    const int uni  = suni;
    const int stride2 = gridDim.x * blockDim.x * 2;
    int e0 = (blockIdx.x * blockDim.x + t) * 2;

    int s0 = 0, s1 = 0, d0 = 0, d1 = 0;
    bool pv = (e0 + 1 < E);
    if (pv) load_idx(ei, (size_t)E, e0, is64, s0, s1, d0, d1);

    while (e0 < E) {
        int e1 = e0 + stride2;
        if (pv) {
            int ns0 = 0, ns1 = 0, nd0 = 0, nd1 = 0;
            bool npv = (e1 + 1 < E);
            if (npv) load_idx(ei, (size_t)E, e1, is64, ns0, ns1, nd0, nd1);

            const float4* apA = (const float4*)(g_xs + (size_t)s0 * 8);
            const float4* bpA = (const float4*)(g_xb + (size_t)d0 * 8);
            const float4* apB = (const float4*)(g_xs + (size_t)s1 * 8);
            const float4* bpB = (const float4*)(g_xb + (size_t)d1 * 8);
            float4 a0A = apA[0], a1A = apA[1], c0A = bpA[0], c1A = bpA[1];
            float4 a0B = apB[0], a1B = apB[1], c0B = bpB[0], c1B = bpB[1];

            float hA[8] = { a0A.x + c0A.x, a0A.y + c0A.y, a0A.z + c0A.z, a0A.w + c0A.w,
                            a1A.x + c1A.x, a1A.y + c1A.y, a1A.z + c1A.z, a1A.w + c1A.w };
            float hB[8] = { a0B.x + c0B.x, a0B.y + c0B.y, a0B.z + c0B.z, a0B.w + c0B.w,
                            a1B.x + c1B.x, a1B.y + c1B.y, a1B.z + c1B.z, a1B.w + c1B.w };

            float h2A[8], h2B[8], h3A[8], h3B[8];
            if (uni) {
                ln_tanh_u(hA);                    ln_tanh_u(hB);
                gemm8(hA, h2A, sW2, sb2);         gemm8(hB, h2B, sW2, sb2);
                ln_tanh_u(h2A);                   ln_tanh_u(h2B);
                gemm8(h2A, h3A, sW3, sb3);        gemm8(h2B, h3B, sW3, sb3);
                ln_tanh_u(h3A);                   ln_tanh_u(h3B);
            } else {
                ln_tanh_g(hA, sg1, skb1);         ln_tanh_g(hB, sg1, skb1);
                gemm8(hA, h2A, sW2, sb2);         gemm8(hB, h2B, sW2, sb2);
                ln_tanh_g(h2A, sg2, skb2);        ln_tanh_g(h2B, sg2, skb2);
                gemm8(h2A, h3A, sW3, sb3);        gemm8(h2B, h3B, sW3, sb3);
                ln_tanh_g(h3A, sg3, skb3);        ln_tanh_g(h3B, sg3, skb3);
            }

            float oA = sb4, oB = sb4;
#pragma unroll
            for (int k = 0; k < 8; k++) { oA = fmaf(h3A[k], sW4[k], oA);
                                          oB = fmaf(h3B[k], sW4[k], oB); }
            *(float2*)(out + e0) = make_float2(oA, oB);

            s0 = ns0; s1 = ns1; d0 = nd0; d1 = nd1;
            pv = npv;
        } else {
            // scalar tail (e0 == E-1, only when E is odd)
            int s, d;
            if (is64) { s = ei[2 * (size_t)e0]; d = ei[2 * ((size_t)E + e0)]; }
            else      { s = ei[e0];             d = ei[(size_t)E + e0]; }
            const float4* ap = (const float4*)(g_xs + (size_t)s * 8);
            const float4* bp = (const float4*)(g_xb + (size_t)d * 8);
            float4 a0 = ap[0], a1 = ap[1], c0 = bp[0], c1 = bp[1];
            float h[8] = { a0.x + c0.x, a0.y + c0.y, a0.z + c0.z, a0.w + c0.w,
                           a1.x + c1.x, a1.y + c1.y, a1.z + c1.z, a1.w + c1.w };
            float h2[8], h3[8];
            if (uni) {
                ln_tanh_u(h);
                gemm8(h, h2, sW2, sb2);
                ln_tanh_u(h2);
                gemm8(h2, h3, sW3, sb3);
                ln_tanh_u(h3);
            } else {
                ln_tanh_g(h, sg1, skb1);
                gemm8(h, h2, sW2, sb2);
                ln_tanh_g(h2, sg2, skb2);
                gemm8(h2, h3, sW3, sb3);
                ln_tanh_g(h3, sg3, skb3);
            }
            float o = sb4;
#pragma unroll
            for (int k = 0; k < 8; k++) o = fmaf(h3[k], sW4[k], o);
            out[e0] = o;
            pv = (e1 + 1 < E);
            if (pv) load_idx(ei, (size_t)E, e1, is64, s0, s1, d0, d1);
        }
        e0 = e1;
    }
}

// ---------------------------------------------------------------------------
extern "C" void kernel_launch(void* const* d_in, const int* in_sizes, int n_in,
                              void* d_out, int out_size)
{
    const float* x     = (const float*)d_in[0];
    const int*   ei    = (const int*)d_in[1];
    const float* vp    = (const float*)d_in[2];
    const int*   batch = (const int*)d_in[3];
    const float* W1  = (const float*)d_in[4];
    const float* b1  = (const float*)d_in[5];
    const float* g1  = (const float*)d_in[6];
    const float* be1 = (const float*)d_in[7];
    const float* W2  = (const float*)d_in[8];
    const float* b2  = (const float*)d_in[9];
    const float* g2  = (const float*)d_in[10];
    const float* be2 = (const float*)d_in[11];
    const float* W3  = (const float*)d_in[12];
    const float* b3  = (const float*)d_in[13];
    const float* g3  = (const float*)d_in[14];
    const float* be3 = (const float*)d_in[15];
    const float* W4  = (const float*)d_in[16];
    const float* b4  = (const float*)d_in[17];

    int N = in_sizes[0] / 16;
    int E = in_sizes[1] / 2;
    int G = in_sizes[2] / 16;

    int pb = (N + 255) / 256;
    pre_k<<<pb, 256>>>(x, batch, vp, W1, b1, ei, N, G);

    // persistent 1-wave grid: 4 blocks/SM x 148 SMs = 16 warps/SM
    int eb = 592;
    long long need = ((long long)E / 2 + 127) / 128;
    if (need < eb) eb = (int)(need > 0 ? need : 1);
    edge_k<<<eb, 128>>>(ei, E, g1, be1, W2, b2, g2, be2, W3, b3, g3, be3,
                        W4, b4, (float*)d_out);
}